// round 2
// baseline (speedup 1.0000x reference)
#include <cuda_runtime.h>
#include <cstdint>

#define KK    1024
#define LL    4087        // 4*K - 9
#define BB    2048
#define NCH   4096        // 2048 batch * {pred,targ}
#define NSTEP 1021        // scan steps (rows 0..1020; row 0 = prologue params)
#define SPAD  1032        // padded rows for prefetch overrun
#define EPSF  1e-6f

// Clip bounds exactly as reference: -1+1e-6, 1-1e-6 (double then f32)
#define CTLO ((float)(-1.0 + 1e-6))
#define CTHI ((float)( 1.0 - 1e-6))

// Scratch: [row][chain] planes.
__device__ float4 g_Q4[(size_t)SPAD * NCH];   // A, B, C, l_t           (67 MB)
__device__ float2 g_Q2[(size_t)SPAD * NCH];   // eps/l1, eps/l0         (34 MB)
__device__ double g_part[128];

__device__ __forceinline__ float clip1(float x) {
    return fminf(fmaxf(x, -1.0f), 1.0f);
}

// ---------------------------------------------------------------------------
// Kernel 1: per-(chain,row) params with smem transpose for coalesced planes.
// Row i (i = 0..1020): A=-cos(theta[i+1]), B=sin*cos(chi[i]), C=sin*sin(chi[i]),
// l = bl[i+2]; q2 = (eps/bl[i+1], eps/bl[i]).
// ---------------------------------------------------------------------------
__global__ __launch_bounds__(256)
void precompute_kernel(const float* __restrict__ pred,
                       const float* __restrict__ targ)
{
    __shared__ float4 s1[32][33];
    __shared__ float2 s2[32][33];

    const int i0 = blockIdx.x * 32;
    const int c0 = blockIdx.y * 32;
    const int x  = threadIdx.x;

    for (int r = threadIdx.y; r < 32; r += 8) {
        const int c = c0 + r;
        const int i = i0 + x;
        if (i < NSTEP) {
            const int b   = c >> 1;
            const int src = c & 1;
            const float* base = (src ? targ : pred) + (size_t)b * LL;

            float s0  = base[2 * i];
            float s1v = base[2 * i + 1];
            float vb0 = base[3064 + i];   // bl[i]
            float vb1 = base[3065 + i];   // bl[i+1]
            float vb2 = base[3066 + i];   // bl[i+2]
            float vd  = base[2043 + i];   // d13[i+1]
            if (src == 0) {
                s0 = clip1(s0); s1v = clip1(s1v);
                vb0 = clip1(vb0); vb1 = clip1(vb1); vb2 = clip1(vb2);
                vd = clip1(vd);
            }
            const float l0 = fmaf(vb0, 1.05f, 1.95f);
            const float l1 = fmaf(vb1, 1.05f, 1.95f);
            const float l2 = fmaf(vb2, 1.05f, 1.95f);
            const float dd = fmaf(vd, 1.75f, 3.25f);

            float ct = (l1 * l1 + l2 * l2 - dd * dd) / (2.0f * l1 * l2);
            ct = fminf(fmaxf(ct, CTLO), CTHI);
            // cancellation-safe sin(arccos(ct))
            const float st = sqrtf((1.0f - ct) * (1.0f + ct));

            const float h2 = s0 * s0 + s1v * s1v;
            float cx, sx;
            if (h2 > 0.0f) {
                const float rin = rsqrtf(h2);
                cx = s1v * rin;
                sx = s0 * rin;
            } else {
                cx = 1.0f; sx = 0.0f;
            }

            float4 q1;
            q1.x = -ct;        // A
            q1.y = st * cx;    // B
            q1.z = st * sx;    // C
            q1.w = l2;         // l_t
            float2 q2;
            q2.x = EPSF / l1;  // eps * inv(prev bond length)   -> hl path
            q2.y = EPSF / l0;  // eps * inv(prev-prev bond len) -> cn path
            s1[r][x] = q1;
            s2[r][x] = q2;
        }
    }
    __syncthreads();

    for (int r = threadIdx.y; r < 32; r += 8) {
        const int i = i0 + r;
        if (i < NSTEP) {
            const int c = c0 + x;
            g_Q4[(size_t)i * NCH + c] = s1[x][r];
            g_Q2[(size_t)i * NCH + c] = s2[x][r];
        }
    }
}

// ---------------------------------------------------------------------------
// Kernel 2: serial scan, one chain per thread, pred/targ paired in lanes.
// Self-normalizing recurrence with scalars folded off the vector chain.
// ---------------------------------------------------------------------------
struct ScanState {
    float Upx, Upy, Upz;   // U_{t-2} raw direction (prev bond / its length)
    float Ux,  Uy,  Uz;    // U_{t-1} raw u-vector
    float px,  py,  pz;    // position
    float acc;
};

__device__ __forceinline__ void scan_iter(ScanState& S, const float4 q1, const float2 q2)
{
    // CR = cross(Up, U)  (prev bond dir x new bond dir)
    const float CRx = fmaf(S.Upy, S.Uz, -S.Upz * S.Uy);
    const float CRy = fmaf(S.Upz, S.Ux, -S.Upx * S.Uz);
    const float CRz = fmaf(S.Upx, S.Uy, -S.Upy * S.Ux);
    // MR = cross(CR, U)  (n x bc direction)
    const float MRx = fmaf(CRy, S.Uz, -CRz * S.Uy);
    const float MRy = fmaf(CRz, S.Ux, -CRx * S.Uz);
    const float MRz = fmaf(CRx, S.Uy, -CRy * S.Ux);

    const float uu = fmaf(S.Ux, S.Ux, fmaf(S.Uy, S.Uy, S.Uz * S.Uz));
    const float cc = fmaf(CRx, CRx, fmaf(CRy, CRy, CRz * CRz));

    // hl = 1/(sqrt(uu) + eps/l1): poly since uu ~ 1 (error < 1e-9)
    const float z  = uu - 1.0f;
    const float d  = fmaf(z, fmaf(-0.125f, z, 0.5f), q2.x);  // sqrt(uu)-1 + eps/l1
    const float hl = fmaf(d, d - 1.0f, 1.0f);                // 1 - d + d^2

    // cn = 1/(sqrt(cc) + eps/kappa): rsqrt + Newton + quadratic eps-correction
    const float rs  = rsqrtf(cc);
    const float a1  = cc * rs;
    const float b1  = a1 * rs;
    const float c1  = fmaf(-0.5f, b1, 1.5f);
    const float rs1 = rs * c1;                 // ~0.5ulp 1/sqrt(cc)
    const float x   = q2.y * rs1;              // (eps/kappa)*rs, kappa ~ l0
    const float cn  = rs1 * fmaf(x, x - 1.0f, 1.0f);
    const float cm  = cn * hl;

    const float al = q1.x * hl;
    const float be = q1.y * cm;
    const float ga = q1.z * cn;

    const float Nx = fmaf(al, S.Ux, fmaf(be, MRx, ga * CRx));
    const float Ny = fmaf(al, S.Uy, fmaf(be, MRy, ga * CRy));
    const float Nz = fmaf(al, S.Uz, fmaf(be, MRz, ga * CRz));

    S.px = fmaf(q1.w, Nx, S.px);
    S.py = fmaf(q1.w, Ny, S.py);
    S.pz = fmaf(q1.w, Nz, S.pz);

    S.Upx = S.Ux; S.Upy = S.Uy; S.Upz = S.Uz;
    S.Ux = Nx; S.Uy = Ny; S.Uz = Nz;

    const float dx = S.px - __shfl_xor_sync(0xffffffffu, S.px, 1);
    const float dy = S.py - __shfl_xor_sync(0xffffffffu, S.py, 1);
    const float dz = S.pz - __shfl_xor_sync(0xffffffffu, S.pz, 1);
    S.acc = fmaf(dx, dx, S.acc);
    S.acc = fmaf(dy, dy, S.acc);
    S.acc = fmaf(dz, dz, S.acc);
}

__global__ __launch_bounds__(32)
void scan_kernel(const float* __restrict__ pred,
                 const float* __restrict__ targ)
{
    const int c   = blockIdx.x * 32 + threadIdx.x;
    const int b   = c >> 1;
    const int src = c & 1;
    const float* base = (src ? targ : pred) + (size_t)b * LL;

    // ---- initial frame (reference-faithful, full precision) ----
    float vb0 = base[3064], vb1 = base[3065], vd = base[2042];
    if (src == 0) { vb0 = clip1(vb0); vb1 = clip1(vb1); vd = clip1(vd); }
    const float bl0 = fmaf(vb0, 1.05f, 1.95f);
    const float bl1 = fmaf(vb1, 1.05f, 1.95f);
    const float d0  = fmaf(vd, 1.75f, 3.25f);
    float ct = (bl0 * bl0 + bl1 * bl1 - d0 * d0) / (2.0f * bl0 * bl1);
    ct = fminf(fmaxf(ct, CTLO), CTHI);
    const float st = sqrtf((1.0f - ct) * (1.0f + ct));

    const float ex = -bl1 * ct;              // a2 - a1
    const float ey =  bl1 * st;
    const float nn = sqrtf(ex * ex + ey * ey);
    const float f  = 1.0f / (nn + EPSF);     // reference's bc normalization
    const float bcx = ex * f, bcy = ey * f;
    const float v   = bl0 * bcy;
    const float nz0 = v / (v + EPSF);        // n0 = (0,0,nz0)
    const float m0x = -nz0 * bcy, m0y = nz0 * bcx;

    // row 0 params -> u_0
    const float4 r0 = g_Q4[c];
    const float U0x = fmaf(r0.x, bcx, r0.y * m0x);
    const float U0y = fmaf(r0.x, bcy, r0.y * m0y);
    const float U0z = r0.z * nz0;

    ScanState S;
    S.px = fmaf(r0.w, U0x, bl0 + ex);        // a3 = a2 + l0*u0
    S.py = fmaf(r0.w, U0y, ey);
    S.pz = r0.w * U0z;
    S.Upx = -ct; S.Upy = st; S.Upz = 0.0f;   // (a2-a1)/bl1 exactly
    S.Ux = U0x; S.Uy = U0y; S.Uz = U0z;
    S.acc = 0.0f;

    {   // a1 diff (x only)
        const float dx = bl0 - __shfl_xor_sync(0xffffffffu, bl0, 1);
        S.acc = fmaf(dx, dx, S.acc);
    }
    {   // a2 diff (x,y)
        const float a2x = bl0 + ex;
        const float dx = a2x - __shfl_xor_sync(0xffffffffu, a2x, 1);
        const float dy = ey  - __shfl_xor_sync(0xffffffffu, ey, 1);
        S.acc = fmaf(dx, dx, S.acc);
        S.acc = fmaf(dy, dy, S.acc);
    }
    {   // a3 diff
        const float dx = S.px - __shfl_xor_sync(0xffffffffu, S.px, 1);
        const float dy = S.py - __shfl_xor_sync(0xffffffffu, S.py, 1);
        const float dz = S.pz - __shfl_xor_sync(0xffffffffu, S.pz, 1);
        S.acc = fmaf(dx, dx, S.acc);
        S.acc = fmaf(dy, dy, S.acc);
        S.acc = fmaf(dz, dz, S.acc);
    }

    // ---- main loop: iterations t = 1..1020, rows 1..1020, groups of 8 ----
    float4 A1[8], B1[8];
    float2 A2[8], B2[8];
    const float4* q4 = g_Q4 + c;
    const float2* q2 = g_Q2 + c;

#pragma unroll
    for (int u = 0; u < 8; u++) {            // rows 1..8
        A1[u] = q4[(size_t)(1 + u) * NCH];
        A2[u] = q2[(size_t)(1 + u) * NCH];
    }

    for (int g = 0; g < 126; g += 2) {
        const size_t rb1 = (size_t)(1 + (g + 1) * 8);
#pragma unroll
        for (int u = 0; u < 8; u++) {
            B1[u] = q4[(rb1 + u) * NCH];
            B2[u] = q2[(rb1 + u) * NCH];
        }
#pragma unroll
        for (int u = 0; u < 8; u++) scan_iter(S, A1[u], A2[u]);

        const size_t rb2 = (size_t)(1 + (g + 2) * 8);
#pragma unroll
        for (int u = 0; u < 8; u++) {
            A1[u] = q4[(rb2 + u) * NCH];
            A2[u] = q2[(rb2 + u) * NCH];
        }
#pragma unroll
        for (int u = 0; u < 8; u++) scan_iter(S, B1[u], B2[u]);
    }
    {   // group 126 (rows 1009..1016) in A; prefetch group 127 (rows 1017..1024)
        const size_t rb = (size_t)(1 + 127 * 8);
#pragma unroll
        for (int u = 0; u < 8; u++) {
            B1[u] = q4[(rb + u) * NCH];
            B2[u] = q2[(rb + u) * NCH];
        }
#pragma unroll
        for (int u = 0; u < 8; u++) scan_iter(S, A1[u], A2[u]);
    }
#pragma unroll
    for (int u = 0; u < 4; u++) scan_iter(S, B1[u], B2[u]);  // rows 1017..1020

    // warp reduction -> deterministic per-block partial
    float acc = S.acc;
#pragma unroll
    for (int off = 16; off; off >>= 1)
        acc += __shfl_xor_sync(0xffffffffu, acc, off);
    if (threadIdx.x == 0)
        g_part[blockIdx.x] = (double)acc;
}

// ---------------------------------------------------------------------------
// Kernel 3: deterministic finalize. Pairs double-count -> /2.
// ---------------------------------------------------------------------------
__global__ void finalize_kernel(float* __restrict__ out)
{
    double s = 0.0;
#pragma unroll 8
    for (int i = 0; i < 128; i++) s += g_part[i];
    out[0] = (float)(s / (2.0 * (double)BB * (double)KK * 3.0));
}

extern "C" void kernel_launch(void* const* d_in, const int* in_sizes, int n_in,
                              void* d_out, int out_size)
{
    const float* pred = (const float*)d_in[0];
    const float* targ = (const float*)d_in[1];

    dim3 pblk(32, 8, 1);
    dim3 pgrd(32, 128, 1);
    precompute_kernel<<<pgrd, pblk>>>(pred, targ);

    scan_kernel<<<128, 32>>>(pred, targ);

    finalize_kernel<<<1, 1>>>((float*)d_out);
}